// round 15
// baseline (speedup 1.0000x reference)
#include <cuda_runtime.h>
#include <cstdint>
#include <cstddef>

// Net_quantize: fused MFL recurrence + LSQ fake-quant + 2 quantized linear layers.
// Warp-autonomous + IMMA fc1. R14: (1) each lane stages ITS OWN row via
// cp.async -> no syncwarp / no swizzle in the staging path (own-data ordering via
// wait_group only); (2) recurrence tracked in W = w/a1 space, killing the
// per-step FMUL. 16 chunks x 8 cols, 4 buffers, prefetch depth 3. fc2 via DP4A.

#define THREADS 256
#define WARPS   8
#define NCOLS   128
#define NCHUNK  16            // 8 cols per chunk; k32 MMA block per 4 chunks

__device__ __forceinline__ void cp_async16(uint32_t saddr, const void* gptr) {
    asm volatile("cp.async.cg.shared.global [%0], [%1], 16;"
                 :: "r"(saddr), "l"(gptr) : "memory");
}
__device__ __forceinline__ void cp_commit() {
    asm volatile("cp.async.commit_group;" ::: "memory");
}
template <int N>
__device__ __forceinline__ void cp_wait() {
    asm volatile("cp.async.wait_group %0;" :: "n"(N) : "memory");
}

__global__ __launch_bounds__(THREADS, 5)
void net_quant_kernel(const float* __restrict__ x,
                      const float* __restrict__ p_alpha,
                      const float* __restrict__ p_beta,
                      const float* __restrict__ p_a1,
                      const float* __restrict__ p_a2,
                      const float* __restrict__ p_a3,
                      const float* __restrict__ W1,
                      const float* __restrict__ b1,
                      const float* __restrict__ p_wa1,
                      const float* __restrict__ W2,
                      const float* __restrict__ b2,
                      const float* __restrict__ p_wa2,
                      float* __restrict__ out)
{
    // per-warp x staging: [warp][buf(4)][slot(2)][lane(32)] float4 = 32 KiB.
    // lane owns column [*][*][lane]: writes AND reads are lane*16B -> clean.
    __shared__ uint4  xw[WARPS][4][2][32];
    __shared__ int    w1B[4][2][32][2];   // W1 B-fragments, 2 KiB
    __shared__ int    w2p[10 * 4];
    __shared__ float  b1s[16];
    __shared__ float  b2s[10];
    __shared__ uint4  sAq[WARPS][64];     // hq tiles, 1 KiB/warp

    const int tid  = threadIdx.x;
    const int wid  = tid >> 5;
    const int lane = tid & 31;
    const int row0 = blockIdx.x * THREADS;

    // this lane stages + computes global row (row0 + wid*32 + lane)
    const float* gsrc = x + (size_t)(row0 + wid * 32 + lane) * NCOLS;
    const uint32_t xw_base = (uint32_t)__cvta_generic_to_shared(&xw[wid][0][0][0]);
    const uint32_t lb = xw_base + (uint32_t)lane * 16u;   // lane's column
    const uint32_t BUFB = 1024u;                           // bytes per buffer

    // ---- issue chunks 0..2 immediately (prefetch depth 3) ----
#pragma unroll
    for (int c0 = 0; c0 < 3; ++c0) {
        const uint32_t b = lb + (uint32_t)c0 * BUFB;
        cp_async16(b,        gsrc + c0 * 8);
        cp_async16(b + 512u, gsrc + c0 * 8 + 4);
        cp_commit();
    }

    // scaled-space recurrence constants: W = w/a1
    const float inv_a1 = 1.0f / p_a1[0];
    const float alphas = p_alpha[0] * inv_a1 * inv_a1;
    const float betas  = p_beta[0] * inv_a1;

    // ---- quantize W1 into per-lane B fragments ----
    {
        const float inv_wa1 = 1.0f / p_wa1[0];
#pragma unroll
        for (int widx = 2 * tid; widx <= 2 * tid + 1; ++widx) {
            const int ln = widx & 31, r = (widx >> 5) & 1;
            const int nt = (widx >> 6) & 1, kt = widx >> 7;
            const int j  = nt * 8 + (ln >> 2);
            const int k0 = kt * 32 + r * 16 + 4 * (ln & 3);
            unsigned v = 0;
#pragma unroll
            for (int b = 0; b < 4; ++b) {
                float t = W1[j * 128 + k0 + b] * inv_wa1;
                int qq;
                asm("cvt.rni.sat.s8.f32 %0, %1;" : "=r"(qq) : "f"(t));
                v = __byte_perm(v, (unsigned)qq, 0x4321);
            }
            w1B[kt][nt][ln][r] = (int)v;
        }
    }
    // ---- quantize + pack W2 (10x16), preload biases ----
    if (tid < 40) {
        const float inv_wa2 = 1.0f / p_wa2[0];
        const int j = tid >> 2, c = tid & 3;
        unsigned v = 0;
#pragma unroll
        for (int b = 0; b < 4; ++b) {
            float t = W2[j * 16 + c * 4 + b] * inv_wa2;
            int qq;
            asm("cvt.rni.sat.s8.f32 %0, %1;" : "=r"(qq) : "f"(t));
            v = __byte_perm(v, (unsigned)qq, 0x4321);
        }
        w2p[tid] = (int)v;
    }
    if (tid >= 64 && tid < 80) b1s[tid - 64] = b1[tid - 64];
    if (tid >= 96 && tid < 106) b2s[tid - 96] = b2[tid - 96];
    __syncthreads();            // the ONLY CTA barrier before the epilogue

    // ---- main loop ----
    float w = inv_a1;           // W0 = 1/a1
    unsigned hpv[4];            // packed hq words for the current k16 pair
    int acc[4][4];
#pragma unroll
    for (int t1 = 0; t1 < 4; ++t1)
#pragma unroll
        for (int t2 = 0; t2 < 4; ++t2) acc[t1][t2] = 0;

    const int rsw = (lane >> 2) & 1;                   // sAq half swizzle
    const uint32_t sA_base = (uint32_t)__cvta_generic_to_shared(&sAq[wid][0]);

#pragma unroll
    for (int c = 0; c < NCHUNK; ++c) {
        if (c < NCHUNK - 3) {
            const uint32_t b = lb + (uint32_t)((c + 3) & 3) * BUFB;
            cp_async16(b,        gsrc + (c + 3) * 8);
            cp_async16(b + 512u, gsrc + (c + 3) * 8 + 4);
            cp_commit();
            cp_wait<3>();       // lane's chunk-c copies retired
        } else if (c == NCHUNK - 3) { cp_wait<2>(); }
        else if (c == NCHUNK - 2)   { cp_wait<1>(); }
        else                        { cp_wait<0>(); }
        // no syncwarp: this lane reads only data IT staged

        // 8 recurrence steps -> 2 packed hq words
        const uint32_t bufb = lb + (uint32_t)(c & 3) * BUFB;
#pragma unroll
        for (int g4 = 0; g4 < 2; ++g4) {
            float4 v;
            asm volatile("ld.shared.v4.f32 {%0,%1,%2,%3}, [%4];"
                         : "=f"(v.x), "=f"(v.y), "=f"(v.z), "=f"(v.w)
                         : "r"(bufb + (uint32_t)g4 * 512u));
            const float xe[4] = {v.x, v.y, v.z, v.w};
            int iq[4];
#pragma unroll
            for (int b = 0; b < 4; ++b) {
                iq[b] = __float2int_rn(w);              // level = rni(W), off-chain
                const float t2 = __fmaf_rn(-betas, xe[b], w);
                float r;
                asm("rcp.approx.f32 %0, %1;" : "=f"(r) : "f"(w));
                w = __fmaf_rn(alphas, r, t2);
            }
            // d = (c<<16) | (sat(a)<<8) | sat(b): b -> low byte
            unsigned ph, pw;
            asm("cvt.pack.sat.s8.s32.b32 %0, %1, %2, %3;"
                : "=r"(ph) : "r"(iq[3]), "r"(iq[2]), "r"(0));
            asm("cvt.pack.sat.s8.s32.b32 %0, %1, %2, %3;"
                : "=r"(pw) : "r"(iq[1]), "r"(iq[0]), "r"(ph));
            hpv[(c & 1) * 2 + g4] = pw;                 // [k0,k1,k2,k3] LE
        }

        if (c & 1) {
            // store k16 half (cols (c-1)*8 .. c*8+7), half-swizzled STS.128
            const unsigned h = (unsigned)((c >> 1) & 1);
            const uint32_t haddr = sA_base + (uint32_t)(lane * 32)
                                 + 16u * (h ^ (unsigned)rsw);
            asm volatile("st.shared.v4.b32 [%0], {%1,%2,%3,%4};"
                         :: "r"(haddr), "r"(hpv[0]), "r"(hpv[1]),
                            "r"(hpv[2]), "r"(hpv[3]) : "memory");
        }

        if ((c & 3) == 3) {     // full k32 staged -> 2 ldmatrix + 4 mma
            __syncwarp();       // cross-lane sAq visibility
            const int kt = c >> 2;
#pragma unroll
            for (int mt = 0; mt < 2; ++mt) {
                const int rowg = mt * 16 + (lane & 15);
                const uint32_t la = sA_base + (uint32_t)(rowg * 32)
                                  + 16u * (unsigned)((lane >> 4) ^ ((rowg >> 2) & 1));
                unsigned a0, a1, a2, a3;
                asm volatile("ldmatrix.sync.aligned.m8n8.x4.shared.b16 "
                             "{%0,%1,%2,%3}, [%4];"
                             : "=r"(a0), "=r"(a1), "=r"(a2), "=r"(a3) : "r"(la));
#pragma unroll
                for (int nt = 0; nt < 2; ++nt) {
                    const int2 bb = *reinterpret_cast<const int2*>(&w1B[kt][nt][lane][0]);
                    asm volatile("mma.sync.aligned.m16n8k32.row.col.s32.s8.s8.s32 "
                                 "{%0,%1,%2,%3}, {%4,%5,%6,%7}, {%8,%9}, {%0,%1,%2,%3};"
                                 : "+r"(acc[mt * 2 + nt][0]), "+r"(acc[mt * 2 + nt][1]),
                                   "+r"(acc[mt * 2 + nt][2]), "+r"(acc[mt * 2 + nt][3])
                                 : "r"(a0), "r"(a1), "r"(a2), "r"(a3),
                                   "r"(bb.x), "r"(bb.y));
                }
            }
            __syncwarp();       // ldmatrix reads done before sAq re-store
        }
    }

    // ---- epilogue (identical to R12) ----
    const float a1  = p_a1[0];
    const float a2  = p_a2[0];
    const float a3  = p_a3[0];
    const float wa1 = p_wa1[0];
    const float wa2 = p_wa2[0];
    const float inv_a2 = 1.0f / a2;
    const float inv_a3 = 1.0f / a3;
    const float s1scale = a1 * wa1;
    const float s2scale = a3 * wa2;

    // scatter quantized s8 levels into sS[32 rows][16 cols] (reuses sAq region)
#pragma unroll
    for (int mt = 0; mt < 2; ++mt) {
#pragma unroll
        for (int nt = 0; nt < 2; ++nt) {
#pragma unroll
            for (int rp = 0; rp < 2; ++rp) {
                const int row = mt * 16 + (lane >> 2) + 8 * rp;
                const int colb = nt * 8 + 2 * (lane & 3);
                unsigned pair = 0;
#pragma unroll
                for (int rr = 0; rr < 2; ++rr) {
                    const int d = acc[mt * 2 + nt][2 * rp + rr];
                    const float h = __fmaf_rn((float)d, s1scale, b1s[colb + rr]);
                    const float sg = __fdividef(1.0f, 1.0f + __expf(-h));
                    float u = sg * inv_a2;
                    u = fminf(fmaxf(u, 0.0f), 255.0f);
                    const float sv = (float)__float2int_rn(u) * a2;
                    const float v2 = sv * inv_a3;
                    int s2q;
                    asm("cvt.rni.sat.s8.f32 %0, %1;" : "=r"(s2q) : "f"(v2));
                    pair |= ((unsigned)s2q & 0xffu) << (8 * rr);
                }
                const uint32_t sa = sA_base + (uint32_t)(row * 16 + colb);
                asm volatile("st.shared.u16 [%0], %1;"
                             :: "r"(sa), "h"((unsigned short)pair) : "memory");
            }
        }
    }
    __syncwarp();

    // fc2: thread = row again
    int4 sp;
    {
        const uint32_t sa = sA_base + (uint32_t)(lane * 16);
        asm volatile("ld.shared.v4.b32 {%0,%1,%2,%3}, [%4];"
                     : "=r"(sp.x), "=r"(sp.y), "=r"(sp.z), "=r"(sp.w) : "r"(sa));
    }

    float* outs = reinterpret_cast<float*>(&xw[wid][0][0][0]);
#pragma unroll
    for (int j = 0; j < 10; ++j) {
        int o = 0;
        o = __dp4a(sp.x, w2p[j * 4 + 0], o);
        o = __dp4a(sp.y, w2p[j * 4 + 1], o);
        o = __dp4a(sp.z, w2p[j * 4 + 2], o);
        o = __dp4a(sp.w, w2p[j * 4 + 3], o);
        outs[lane * 10 + j] = __fmaf_rn((float)o, s2scale, b2s[j]);
    }
    __syncwarp();

    // coalesced per-warp store: 320 contiguous floats
    const size_t obase = (size_t)(row0 + wid * 32) * 10;
#pragma unroll
    for (int t = 0; t < 10; ++t) {
        const int i = t * 32 + lane;
        out[obase + i] = outs[i];
    }
}

extern "C" void kernel_launch(void* const* d_in, const int* in_sizes, int n_in,
                              void* d_out, int out_size)
{
    const float* x       = (const float*)d_in[0];
    const float* p_alpha = (const float*)d_in[1];
    const float* p_beta  = (const float*)d_in[2];
    const float* p_a1    = (const float*)d_in[3];
    const float* p_a2    = (const float*)d_in[4];
    const float* p_a3    = (const float*)d_in[5];
    const float* W1      = (const float*)d_in[6];
    const float* b1      = (const float*)d_in[7];
    const float* p_wa1   = (const float*)d_in[8];
    const float* W2      = (const float*)d_in[9];
    const float* b2      = (const float*)d_in[10];
    const float* p_wa2   = (const float*)d_in[11];
    float* out = (float*)d_out;

    const int M = in_sizes[0] / NCOLS;     // 262144
    const int blocks = M / THREADS;        // 1024

    net_quant_kernel<<<blocks, THREADS>>>(x, p_alpha, p_beta, p_a1, p_a2, p_a3,
                                          W1, b1, p_wa1, W2, b2, p_wa2, out);
}

// round 16
// speedup vs baseline: 1.2890x; 1.2890x over previous
#include <cuda_runtime.h>
#include <cstdint>
#include <cstddef>

// Net_quantize: fused MFL recurrence + LSQ fake-quant + 2 quantized linear layers.
// R15 = R12 (best measured: warp-autonomous, coalesced cp.async staging depth 3,
// IMMA fc1, DP4A fc2) + scaled recurrence W = w/a1 (removes the per-step FMUL;
// numerically validated in R14, rel_err 4.2e-4).

#define THREADS 256
#define WARPS   8
#define NCOLS   128
#define NCHUNK  16            // 8 cols per chunk; k32 MMA block per 4 chunks

__device__ __forceinline__ void cp_async16(uint32_t saddr, const void* gptr) {
    asm volatile("cp.async.cg.shared.global [%0], [%1], 16;"
                 :: "r"(saddr), "l"(gptr) : "memory");
}
__device__ __forceinline__ void cp_commit() {
    asm volatile("cp.async.commit_group;" ::: "memory");
}
template <int N>
__device__ __forceinline__ void cp_wait() {
    asm volatile("cp.async.wait_group %0;" :: "n"(N) : "memory");
}

__global__ __launch_bounds__(THREADS, 5)
void net_quant_kernel(const float* __restrict__ x,
                      const float* __restrict__ p_alpha,
                      const float* __restrict__ p_beta,
                      const float* __restrict__ p_a1,
                      const float* __restrict__ p_a2,
                      const float* __restrict__ p_a3,
                      const float* __restrict__ W1,
                      const float* __restrict__ b1,
                      const float* __restrict__ p_wa1,
                      const float* __restrict__ W2,
                      const float* __restrict__ b2,
                      const float* __restrict__ p_wa2,
                      float* __restrict__ out)
{
    // per-warp x staging: [warp][buf(4)][row(32)][slot(2)] float4 = 32 KiB
    __shared__ float4 xw[WARPS][4][32][2];
    // W1 int8 B-fragments: [kt(4)][nt(2)][lane(32)][r(2)] = 2 KiB
    __shared__ int    w1B[4][2][32][2];
    __shared__ int    w2p[10 * 4];
    __shared__ float  b1s[16];
    __shared__ float  b2s[10];
    // per-warp hq tile: 32 rows x 32 bytes (k32), half-swizzled = 1 KiB/warp
    __shared__ uint4  sAq[WARPS][64];

    const int tid  = threadIdx.x;
    const int wid  = tid >> 5;
    const int lane = tid & 31;
    const int row0 = blockIdx.x * THREADS;

    // staging geometry (R12): lane stages quad q_s of rows row_s and row_s+16
    const int row_s = lane >> 1, q_s = lane & 1;
    const int slot_w = q_s ^ ((row_s >> 2) & 1);   // same for row_s+16

    const float* gsrc = x + (size_t)(row0 + wid * 32 + row_s) * NCOLS + q_s * 4;
    const uint32_t xw_base = (uint32_t)__cvta_generic_to_shared(&xw[wid][0][0][0]);
    const uint32_t soff = (uint32_t)(row_s * 32 + slot_w * 16);    // within buffer
    const uint32_t BUFB = 1024u;                                   // bytes per buffer

    // ---- issue chunks 0..2 immediately (prefetch depth 3) ----
#pragma unroll
    for (int c0 = 0; c0 < 3; ++c0) {
        const uint32_t b = xw_base + (uint32_t)c0 * BUFB + soff;
        const float* g = gsrc + c0 * 8;
        cp_async16(b,        g);
        cp_async16(b + 512u, g + (size_t)16 * NCOLS);   // +16 rows
        cp_commit();
    }

    // scaled-space recurrence constants: W = w/a1
    const float inv_a1 = 1.0f / p_a1[0];
    const float alphas = p_alpha[0] * inv_a1 * inv_a1;
    const float betas  = p_beta[0] * inv_a1;

    // ---- quantize W1 into per-lane B fragments ----
    {
        const float inv_wa1 = 1.0f / p_wa1[0];
#pragma unroll
        for (int widx = 2 * tid; widx <= 2 * tid + 1; ++widx) {
            const int ln = widx & 31, r = (widx >> 5) & 1;
            const int nt = (widx >> 6) & 1, kt = widx >> 7;
            const int j  = nt * 8 + (ln >> 2);
            const int k0 = kt * 32 + r * 16 + 4 * (ln & 3);
            unsigned v = 0;
#pragma unroll
            for (int b = 0; b < 4; ++b) {
                float t = W1[j * 128 + k0 + b] * inv_wa1;
                int qq;
                asm("cvt.rni.sat.s8.f32 %0, %1;" : "=r"(qq) : "f"(t));
                v = __byte_perm(v, (unsigned)qq, 0x4321);
            }
            w1B[kt][nt][ln][r] = (int)v;
        }
    }
    // ---- quantize + pack W2 (10x16), preload biases ----
    if (tid < 40) {
        const float inv_wa2 = 1.0f / p_wa2[0];
        const int j = tid >> 2, c = tid & 3;
        unsigned v = 0;
#pragma unroll
        for (int b = 0; b < 4; ++b) {
            float t = W2[j * 16 + c * 4 + b] * inv_wa2;
            int qq;
            asm("cvt.rni.sat.s8.f32 %0, %1;" : "=r"(qq) : "f"(t));
            v = __byte_perm(v, (unsigned)qq, 0x4321);
        }
        w2p[tid] = (int)v;
    }
    if (tid >= 64 && tid < 80) b1s[tid - 64] = b1[tid - 64];
    if (tid >= 96 && tid < 106) b2s[tid - 96] = b2[tid - 96];
    __syncthreads();            // the ONLY CTA barrier before the epilogue

    // ---- main loop ----
    float w = inv_a1;           // W0 = 1/a1
    unsigned hpv[4];            // packed hq words for the current k16 pair
    int acc[4][4];
#pragma unroll
    for (int t1 = 0; t1 < 4; ++t1)
#pragma unroll
        for (int t2 = 0; t2 < 4; ++t2) acc[t1][t2] = 0;

    const int rsw = (lane >> 2) & 1;                   // read-slot swizzle bit
    const uint32_t sA_base = (uint32_t)__cvta_generic_to_shared(&sAq[wid][0]);
    const uint32_t xr_base = xw_base + (uint32_t)(lane * 32);

#pragma unroll
    for (int c = 0; c < NCHUNK; ++c) {
        if (c < NCHUNK - 3) {
            const uint32_t b = xw_base + (uint32_t)((c + 3) & 3) * BUFB + soff;
            const float* g = gsrc + (c + 3) * 8;
            cp_async16(b,        g);
            cp_async16(b + 512u, g + (size_t)16 * NCOLS);
            cp_commit();
            cp_wait<3>();       // chunk c's group retired
        } else if (c == NCHUNK - 3) { cp_wait<2>(); }
        else if (c == NCHUNK - 2)   { cp_wait<1>(); }
        else                        { cp_wait<0>(); }
        __syncwarp();           // chunk-c x visible warp-wide

        // 8 recurrence steps -> 2 packed hq words
        const uint32_t bufb = xr_base + (uint32_t)(c & 3) * BUFB;
#pragma unroll
        for (int g4 = 0; g4 < 2; ++g4) {
            float4 v;
            {
                const uint32_t la = bufb + 16u * (unsigned)(g4 ^ rsw);
                asm volatile("ld.shared.v4.f32 {%0,%1,%2,%3}, [%4];"
                             : "=f"(v.x), "=f"(v.y), "=f"(v.z), "=f"(v.w)
                             : "r"(la));
            }
            const float xe[4] = {v.x, v.y, v.z, v.w};
            int iq[4];
#pragma unroll
            for (int b = 0; b < 4; ++b) {
                iq[b] = __float2int_rn(w);              // level = rni(W), off-chain
                const float t2 = __fmaf_rn(-betas, xe[b], w);
                float r;
                asm("rcp.approx.f32 %0, %1;" : "=f"(r) : "f"(w));
                w = __fmaf_rn(alphas, r, t2);
            }
            // d = (c<<16) | (sat(a)<<8) | sat(b): b -> low byte
            unsigned ph, pw;
            asm("cvt.pack.sat.s8.s32.b32 %0, %1, %2, %3;"
                : "=r"(ph) : "r"(iq[3]), "r"(iq[2]), "r"(0));
            asm("cvt.pack.sat.s8.s32.b32 %0, %1, %2, %3;"
                : "=r"(pw) : "r"(iq[1]), "r"(iq[0]), "r"(ph));
            hpv[(c & 1) * 2 + g4] = pw;                 // [k0,k1,k2,k3] LE
        }

        if (c & 1) {
            // store k16 half (cols (c-1)*8 .. c*8+7), half-swizzled STS.128
            const unsigned h = (unsigned)((c >> 1) & 1);
            const uint32_t haddr = sA_base + (uint32_t)(lane * 32)
                                 + 16u * (h ^ (unsigned)rsw);
            asm volatile("st.shared.v4.b32 [%0], {%1,%2,%3,%4};"
                         :: "r"(haddr), "r"(hpv[0]), "r"(hpv[1]),
                            "r"(hpv[2]), "r"(hpv[3]) : "memory");
        }

        if ((c & 3) == 3) {     // full k32 staged -> 2 ldmatrix + 4 mma
            __syncwarp();
            const int kt = c >> 2;
#pragma unroll
            for (int mt = 0; mt < 2; ++mt) {
                const int rowg = mt * 16 + (lane & 15);
                const uint32_t la = sA_base + (uint32_t)(rowg * 32)
                                  + 16u * (unsigned)((lane >> 4) ^ ((rowg >> 2) & 1));
                unsigned a0, a1, a2, a3;
                asm volatile("ldmatrix.sync.aligned.m8n8.x4.shared.b16 "
                             "{%0,%1,%2,%3}, [%4];"
                             : "=r"(a0), "=r"(a1), "=r"(a2), "=r"(a3) : "r"(la));
#pragma unroll
                for (int nt = 0; nt < 2; ++nt) {
                    const int2 bb = *reinterpret_cast<const int2*>(&w1B[kt][nt][lane][0]);
                    asm volatile("mma.sync.aligned.m16n8k32.row.col.s32.s8.s8.s32 "
                                 "{%0,%1,%2,%3}, {%4,%5,%6,%7}, {%8,%9}, {%0,%1,%2,%3};"
                                 : "+r"(acc[mt * 2 + nt][0]), "+r"(acc[mt * 2 + nt][1]),
                                   "+r"(acc[mt * 2 + nt][2]), "+r"(acc[mt * 2 + nt][3])
                                 : "r"(a0), "r"(a1), "r"(a2), "r"(a3),
                                   "r"(bb.x), "r"(bb.y));
                }
            }
            __syncwarp();       // ldmatrix reads done before sA re-store
        }
    }

    // ---- epilogue (identical to R12) ----
    const float a1  = p_a1[0];
    const float a2  = p_a2[0];
    const float a3  = p_a3[0];
    const float wa1 = p_wa1[0];
    const float wa2 = p_wa2[0];
    const float inv_a2 = 1.0f / a2;
    const float inv_a3 = 1.0f / a3;
    const float s1scale = a1 * wa1;
    const float s2scale = a3 * wa2;

    // scatter quantized s8 levels into sS[32 rows][16 cols] (reuses sA region)
#pragma unroll
    for (int mt = 0; mt < 2; ++mt) {
#pragma unroll
        for (int nt = 0; nt < 2; ++nt) {
#pragma unroll
            for (int rp = 0; rp < 2; ++rp) {
                const int row = mt * 16 + (lane >> 2) + 8 * rp;
                const int colb = nt * 8 + 2 * (lane & 3);
                unsigned pair = 0;
#pragma unroll
                for (int rr = 0; rr < 2; ++rr) {
                    const int d = acc[mt * 2 + nt][2 * rp + rr];
                    const float h = __fmaf_rn((float)d, s1scale, b1s[colb + rr]);
                    const float sg = __fdividef(1.0f, 1.0f + __expf(-h));
                    float u = sg * inv_a2;
                    u = fminf(fmaxf(u, 0.0f), 255.0f);
                    const float sv = (float)__float2int_rn(u) * a2;
                    const float v2 = sv * inv_a3;
                    int s2q;
                    asm("cvt.rni.sat.s8.f32 %0, %1;" : "=r"(s2q) : "f"(v2));
                    pair |= ((unsigned)s2q & 0xffu) << (8 * rr);
                }
                const uint32_t sa = sA_base + (uint32_t)(row * 16 + colb);
                asm volatile("st.shared.u16 [%0], %1;"
                             :: "r"(sa), "h"((unsigned short)pair) : "memory");
            }
        }
    }
    __syncwarp();

    // fc2: thread = row again
    int4 sp;
    {
        const uint32_t sa = sA_base + (uint32_t)(lane * 16);
        asm volatile("ld.shared.v4.b32 {%0,%1,%2,%3}, [%4];"
                     : "=r"(sp.x), "=r"(sp.y), "=r"(sp.z), "=r"(sp.w) : "r"(sa));
    }

    float* outs = reinterpret_cast<float*>(&xw[wid][0][0][0]);
#pragma unroll
    for (int j = 0; j < 10; ++j) {
        int o = 0;
        o = __dp4a(sp.x, w2p[j * 4 + 0], o);
        o = __dp4a(sp.y, w2p[j * 4 + 1], o);
        o = __dp4a(sp.z, w2p[j * 4 + 2], o);
        o = __dp4a(sp.w, w2p[j * 4 + 3], o);
        outs[lane * 10 + j] = __fmaf_rn((float)o, s2scale, b2s[j]);
    }
    __syncwarp();

    // coalesced per-warp store: 320 contiguous floats
    const size_t obase = (size_t)(row0 + wid * 32) * 10;
#pragma unroll
    for (int t = 0; t < 10; ++t) {
        const int i = t * 32 + lane;
        out[obase + i] = outs[i];
    }
}

extern "C" void kernel_launch(void* const* d_in, const int* in_sizes, int n_in,
                              void* d_out, int out_size)
{
    const float* x       = (const float*)d_in[0];
    const float* p_alpha = (const float*)d_in[1];
    const float* p_beta  = (const float*)d_in[2];
    const float* p_a1    = (const float*)d_in[3];
    const float* p_a2    = (const float*)d_in[4];
    const float* p_a3    = (const float*)d_in[5];
    const float* W1      = (const float*)d_in[6];
    const float* b1      = (const float*)d_in[7];
    const float* p_wa1   = (const float*)d_in[8];
    const float* W2      = (const float*)d_in[9];
    const float* b2      = (const float*)d_in[10];
    const float* p_wa2   = (const float*)d_in[11];
    float* out = (float*)d_out;

    const int M = in_sizes[0] / NCOLS;     // 262144
    const int blocks = M / THREADS;        // 1024

    net_quant_kernel<<<blocks, THREADS>>>(x, p_alpha, p_beta, p_a1, p_a2, p_a3,
                                          W1, b1, p_wa1, W2, b2, p_wa2, out);
}

// round 17
// speedup vs baseline: 1.3288x; 1.0308x over previous
#include <cuda_runtime.h>
#include <cstdint>
#include <cstddef>

// Net_quantize: fused MFL recurrence + LSQ fake-quant + 2 quantized linear layers.
// R16 = R12 skeleton (warp-autonomous, coalesced cp.async staging, IMMA fc1,
// DP4A fc2) + paired-chunk main loop: 8 outer iterations x 16 cols, halving
// cp_wait/__syncwarp pairs and loop overhead. Scaled recurrence W = w/a1
// (rel_err 4.2e-4, verified R14/R15). Prologue fills all 4 buffers.

#define THREADS 256
#define WARPS   8
#define NCOLS   128

__device__ __forceinline__ void cp_async16(uint32_t saddr, const void* gptr) {
    asm volatile("cp.async.cg.shared.global [%0], [%1], 16;"
                 :: "r"(saddr), "l"(gptr) : "memory");
}
__device__ __forceinline__ void cp_commit() {
    asm volatile("cp.async.commit_group;" ::: "memory");
}
template <int N>
__device__ __forceinline__ void cp_wait() {
    asm volatile("cp.async.wait_group %0;" :: "n"(N) : "memory");
}

__global__ __launch_bounds__(THREADS, 5)
void net_quant_kernel(const float* __restrict__ x,
                      const float* __restrict__ p_alpha,
                      const float* __restrict__ p_beta,
                      const float* __restrict__ p_a1,
                      const float* __restrict__ p_a2,
                      const float* __restrict__ p_a3,
                      const float* __restrict__ W1,
                      const float* __restrict__ b1,
                      const float* __restrict__ p_wa1,
                      const float* __restrict__ W2,
                      const float* __restrict__ b2,
                      const float* __restrict__ p_wa2,
                      float* __restrict__ out)
{
    // per-warp x staging: [warp][buf(4)][row(32)][slot(2)] float4 = 32 KiB
    __shared__ float4 xw[WARPS][4][32][2];
    // W1 int8 B-fragments: [kt(4)][nt(2)][lane(32)][r(2)] = 2 KiB
    __shared__ int    w1B[4][2][32][2];
    __shared__ int    w2p[10 * 4];
    __shared__ float  b1s[16];
    __shared__ float  b2s[10];
    // per-warp hq tile: 32 rows x 32 bytes (k32), half-swizzled = 1 KiB/warp
    __shared__ uint4  sAq[WARPS][64];

    const int tid  = threadIdx.x;
    const int wid  = tid >> 5;
    const int lane = tid & 31;
    const int row0 = blockIdx.x * THREADS;

    // staging geometry (R12): lane stages quad q_s of rows row_s and row_s+16
    const int row_s = lane >> 1, q_s = lane & 1;
    const int slot_w = q_s ^ ((row_s >> 2) & 1);   // same for row_s+16

    const float* gsrc = x + (size_t)(row0 + wid * 32 + row_s) * NCOLS + q_s * 4;
    const uint32_t xw_base = (uint32_t)__cvta_generic_to_shared(&xw[wid][0][0][0]);
    const uint32_t soff = (uint32_t)(row_s * 32 + slot_w * 16);    // within buffer
    const uint32_t BUFB = 1024u;                                   // bytes per buffer

    // ---- prologue: fill all 4 buffers (chunks 0..3, 4 commit groups) ----
#pragma unroll
    for (int c0 = 0; c0 < 4; ++c0) {
        const uint32_t b = xw_base + (uint32_t)c0 * BUFB + soff;
        const float* g = gsrc + c0 * 8;
        cp_async16(b,        g);
        cp_async16(b + 512u, g + (size_t)16 * NCOLS);   // +16 rows
        cp_commit();
    }

    // scaled-space recurrence constants: W = w/a1
    const float inv_a1 = 1.0f / p_a1[0];
    const float alphas = p_alpha[0] * inv_a1 * inv_a1;
    const float betas  = p_beta[0] * inv_a1;

    // ---- quantize W1 into per-lane B fragments ----
    {
        const float inv_wa1 = 1.0f / p_wa1[0];
#pragma unroll
        for (int widx = 2 * tid; widx <= 2 * tid + 1; ++widx) {
            const int ln = widx & 31, r = (widx >> 5) & 1;
            const int nt = (widx >> 6) & 1, kt = widx >> 7;
            const int j  = nt * 8 + (ln >> 2);
            const int k0 = kt * 32 + r * 16 + 4 * (ln & 3);
            unsigned v = 0;
#pragma unroll
            for (int b = 0; b < 4; ++b) {
                float t = W1[j * 128 + k0 + b] * inv_wa1;
                int qq;
                asm("cvt.rni.sat.s8.f32 %0, %1;" : "=r"(qq) : "f"(t));
                v = __byte_perm(v, (unsigned)qq, 0x4321);
            }
            w1B[kt][nt][ln][r] = (int)v;
        }
    }
    // ---- quantize + pack W2 (10x16), preload biases ----
    if (tid < 40) {
        const float inv_wa2 = 1.0f / p_wa2[0];
        const int j = tid >> 2, c = tid & 3;
        unsigned v = 0;
#pragma unroll
        for (int b = 0; b < 4; ++b) {
            float t = W2[j * 16 + c * 4 + b] * inv_wa2;
            int qq;
            asm("cvt.rni.sat.s8.f32 %0, %1;" : "=r"(qq) : "f"(t));
            v = __byte_perm(v, (unsigned)qq, 0x4321);
        }
        w2p[tid] = (int)v;
    }
    if (tid >= 64 && tid < 80) b1s[tid - 64] = b1[tid - 64];
    if (tid >= 96 && tid < 106) b2s[tid - 96] = b2[tid - 96];
    __syncthreads();            // the ONLY CTA barrier before the epilogue

    // ---- main loop: 8 outer iterations, 2 chunks (16 cols) each ----
    float w = inv_a1;           // W0 = 1/a1
    int acc[4][4];
#pragma unroll
    for (int t1 = 0; t1 < 4; ++t1)
#pragma unroll
        for (int t2 = 0; t2 < 4; ++t2) acc[t1][t2] = 0;

    const int rsw = (lane >> 2) & 1;                   // read-slot swizzle bit
    const uint32_t sA_base = (uint32_t)__cvta_generic_to_shared(&sAq[wid][0]);
    const uint32_t xr_base = xw_base + (uint32_t)(lane * 32);

#pragma unroll
    for (int i = 0; i < 8; ++i) {
        // retire the pair (chunks 2i, 2i+1); keep next pair in flight
        if (i < 7) { cp_wait<2>(); } else { cp_wait<0>(); }
        __syncwarp();           // pair visible warp-wide

        // 16 recurrence steps -> 4 packed hq words (one k16 half)
        unsigned hpv[4];
#pragma unroll
        for (int cc = 0; cc < 2; ++cc) {
            const int c = 2 * i + cc;
            const uint32_t bufb = xr_base + (uint32_t)(c & 3) * BUFB;
#pragma unroll
            for (int g4 = 0; g4 < 2; ++g4) {
                float4 v;
                {
                    const uint32_t la = bufb + 16u * (unsigned)(g4 ^ rsw);
                    asm volatile("ld.shared.v4.f32 {%0,%1,%2,%3}, [%4];"
                                 : "=f"(v.x), "=f"(v.y), "=f"(v.z), "=f"(v.w)
                                 : "r"(la));
                }
                const float xe[4] = {v.x, v.y, v.z, v.w};
                int iq[4];
#pragma unroll
                for (int b = 0; b < 4; ++b) {
                    iq[b] = __float2int_rn(w);          // level = rni(W), off-chain
                    const float t2 = __fmaf_rn(-betas, xe[b], w);
                    float r;
                    asm("rcp.approx.f32 %0, %1;" : "=f"(r) : "f"(w));
                    w = __fmaf_rn(alphas, r, t2);
                }
                // d = (c<<16) | (sat(a)<<8) | sat(b): b -> low byte
                unsigned ph, pw;
                asm("cvt.pack.sat.s8.s32.b32 %0, %1, %2, %3;"
                    : "=r"(ph) : "r"(iq[3]), "r"(iq[2]), "r"(0));
                asm("cvt.pack.sat.s8.s32.b32 %0, %1, %2, %3;"
                    : "=r"(pw) : "r"(iq[1]), "r"(iq[0]), "r"(ph));
                hpv[cc * 2 + g4] = pw;                  // [k0,k1,k2,k3] LE
            }
        }

        // store k16 half (cols i*16 .. i*16+15), half-swizzled STS.128
        {
            const unsigned h = (unsigned)(i & 1);
            const uint32_t haddr = sA_base + (uint32_t)(lane * 32)
                                 + 16u * (h ^ (unsigned)rsw);
            asm volatile("st.shared.v4.b32 [%0], {%1,%2,%3,%4};"
                         :: "r"(haddr), "r"(hpv[0]), "r"(hpv[1]),
                            "r"(hpv[2]), "r"(hpv[3]) : "memory");
        }

        if (i & 1) {            // full k32 staged -> 2 ldmatrix + 4 mma
            __syncwarp();
            const int kt = i >> 1;
#pragma unroll
            for (int mt = 0; mt < 2; ++mt) {
                const int rowg = mt * 16 + (lane & 15);
                const uint32_t la = sA_base + (uint32_t)(rowg * 32)
                                  + 16u * (unsigned)((lane >> 4) ^ ((rowg >> 2) & 1));
                unsigned a0, a1, a2, a3;
                asm volatile("ldmatrix.sync.aligned.m8n8.x4.shared.b16 "
                             "{%0,%1,%2,%3}, [%4];"
                             : "=r"(a0), "=r"(a1), "=r"(a2), "=r"(a3) : "r"(la));
#pragma unroll
                for (int nt = 0; nt < 2; ++nt) {
                    const int2 bb = *reinterpret_cast<const int2*>(&w1B[kt][nt][lane][0]);
                    asm volatile("mma.sync.aligned.m16n8k32.row.col.s32.s8.s8.s32 "
                                 "{%0,%1,%2,%3}, {%4,%5,%6,%7}, {%8,%9}, {%0,%1,%2,%3};"
                                 : "+r"(acc[mt * 2 + nt][0]), "+r"(acc[mt * 2 + nt][1]),
                                   "+r"(acc[mt * 2 + nt][2]), "+r"(acc[mt * 2 + nt][3])
                                 : "r"(a0), "r"(a1), "r"(a2), "r"(a3),
                                   "r"(bb.x), "r"(bb.y));
                }
            }
            __syncwarp();       // ldmatrix reads done before sA re-store
        }

        // refill the just-consumed buffers with chunks 2i+4, 2i+5
        if (i < 6) {
#pragma unroll
            for (int cc = 0; cc < 2; ++cc) {
                const int cn = 2 * i + 4 + cc;
                const uint32_t b = xw_base + (uint32_t)(cn & 3) * BUFB + soff;
                const float* g = gsrc + cn * 8;
                cp_async16(b,        g);
                cp_async16(b + 512u, g + (size_t)16 * NCOLS);
                cp_commit();
            }
        }
    }

    // ---- epilogue (identical to R12) ----
    const float a1  = p_a1[0];
    const float a2  = p_a2[0];
    const float a3  = p_a3[0];
    const float wa1 = p_wa1[0];
    const float wa2 = p_wa2[0];
    const float inv_a2 = 1.0f / a2;
    const float inv_a3 = 1.0f / a3;
    const float s1scale = a1 * wa1;
    const float s2scale = a3 * wa2;

    // scatter quantized s8 levels into sS[32 rows][16 cols] (reuses sA region)
#pragma unroll
    for (int mt = 0; mt < 2; ++mt) {
#pragma unroll
        for (int nt = 0; nt < 2; ++nt) {
#pragma unroll
            for (int rp = 0; rp < 2; ++rp) {
                const int row = mt * 16 + (lane >> 2) + 8 * rp;
                const int colb = nt * 8 + 2 * (lane & 3);
                unsigned pair = 0;
#pragma unroll
                for (int rr = 0; rr < 2; ++rr) {
                    const int d = acc[mt * 2 + nt][2 * rp + rr];
                    const float h = __fmaf_rn((float)d, s1scale, b1s[colb + rr]);
                    const float sg = __fdividef(1.0f, 1.0f + __expf(-h));
                    float u = sg * inv_a2;
                    u = fminf(fmaxf(u, 0.0f), 255.0f);
                    const float sv = (float)__float2int_rn(u) * a2;
                    const float v2 = sv * inv_a3;
                    int s2q;
                    asm("cvt.rni.sat.s8.f32 %0, %1;" : "=r"(s2q) : "f"(v2));
                    pair |= ((unsigned)s2q & 0xffu) << (8 * rr);
                }
                const uint32_t sa = sA_base + (uint32_t)(row * 16 + colb);
                asm volatile("st.shared.u16 [%0], %1;"
                             :: "r"(sa), "h"((unsigned short)pair) : "memory");
            }
        }
    }
    __syncwarp();

    // fc2: thread = row again
    int4 sp;
    {
        const uint32_t sa = sA_base + (uint32_t)(lane * 16);
        asm volatile("ld.shared.v4.b32 {%0,%1,%2,%3}, [%4];"
                     : "=r"(sp.x), "=r"(sp.y), "=r"(sp.z), "=r"(sp.w) : "r"(sa));
    }

    float* outs = reinterpret_cast<float*>(&xw[wid][0][0][0]);
#pragma unroll
    for (int j = 0; j < 10; ++j) {
        int o = 0;
        o = __dp4a(sp.x, w2p[j * 4 + 0], o);
        o = __dp4a(sp.y, w2p[j * 4 + 1], o);
        o = __dp4a(sp.z, w2p[j * 4 + 2], o);
        o = __dp4a(sp.w, w2p[j * 4 + 3], o);
        outs[lane * 10 + j] = __fmaf_rn((float)o, s2scale, b2s[j]);
    }
    __syncwarp();

    // coalesced per-warp store: 320 contiguous floats
    const size_t obase = (size_t)(row0 + wid * 32) * 10;
#pragma unroll
    for (int t = 0; t < 10; ++t) {
        const int i = t * 32 + lane;
        out[obase + i] = outs[i];
    }
}

extern "C" void kernel_launch(void* const* d_in, const int* in_sizes, int n_in,
                              void* d_out, int out_size)
{
    const float* x       = (const float*)d_in[0];
    const float* p_alpha = (const float*)d_in[1];
    const float* p_beta  = (const float*)d_in[2];
    const float* p_a1    = (const float*)d_in[3];
    const float* p_a2    = (const float*)d_in[4];
    const float* p_a3    = (const float*)d_in[5];
    const float* W1      = (const float*)d_in[6];
    const float* b1      = (const float*)d_in[7];
    const float* p_wa1   = (const float*)d_in[8];
    const float* W2      = (const float*)d_in[9];
    const float* b2      = (const float*)d_in[10];
    const float* p_wa2   = (const float*)d_in[11];
    float* out = (float*)d_out;

    const int M = in_sizes[0] / NCOLS;     // 262144
    const int blocks = M / THREADS;        // 1024

    net_quant_kernel<<<blocks, THREADS>>>(x, p_alpha, p_beta, p_a1, p_a2, p_a3,
                                          W1, b1, p_wa1, W2, b2, p_wa2, out);
}